// round 9
// baseline (speedup 1.0000x reference)
#include <cuda_runtime.h>
#include <cuda_fp16.h>
#include <math.h>
#include <stdint.h>

// N=50000, E=800000, C_IN=128, C_HID=128, C_OUT=64
#define CIN  128
#define CHID 128
#define COUT 64
#define MAXN 50048
#define MAXE 800000
#define MAXB 256   // max scan blocks (ceil(50048/256) = 196)

// -------- scratch (device globals) --------
__device__ float g_deg[MAXN];
__device__ float g_dinv[MAXN];
__device__ int   g_cnt[MAXN];
__device__ int   g_off[MAXN + 1];
__device__ int   g_cur[MAXN];
__device__ int   g_part[MAXB];
__device__ int   g_csr_src[MAXE];
__device__ float g_csr_norm[MAXE];
__device__ __half g_xw1h[(size_t)MAXN * CHID];   // x @ W1, fp16 (gathered by agg1)
__device__ float  g_h  [(size_t)MAXN * CHID];    // elu(conv1), fp32 (streamed by GEMM2)
__device__ __half g_xw2h[(size_t)MAXN * COUT];   // h @ W2, fp16 (gathered by agg2)
__device__ int   g_idx64;

// -------- packed f32x2 helpers (base sm_100-family PTX; NOT an 'a' feature) --------
#define FMA_F32X2(d, a, b, c) \
    asm("fma.rn.f32x2 %0, %1, %2, %3;" : "=l"(d) : "l"(a), "l"(b), "l"(c))
#define PACK_DUP_F32X2(out, f) \
    asm("mov.b64 %0, {%1, %1};" : "=l"(out) : "r"(__float_as_uint(f)))
#define UNPACK_F32X2(lo, hi, in) \
    asm("mov.b64 {%0, %1}, %2;" : "=r"(lo), "=r"(hi) : "l"(in))

// -------- zero + warp-parallel edge-index width detection --------
__global__ void k_zero(const int* __restrict__ ei, int words, int n) {
    int i = blockIdx.x * blockDim.x + threadIdx.x;
    if (i < n) { g_deg[i] = 0.0f; g_cnt[i] = 0; }
    if (blockIdx.x == 0 && threadIdx.x < 32) {
        int t = threadIdx.x;
        int i1 = 1 + 2 * t, i2 = 65 + 2 * t;
        int nz = 0;
        if (i1 < words && ei[i1] != 0) nz = 1;
        if (i2 < words && ei[i2] != 0) nz = 1;
        unsigned b = __ballot_sync(0xFFFFFFFFu, nz);
        if (t == 0) g_idx64 = (b == 0u) ? 1 : 0;
    }
}

__device__ __forceinline__ void edge_sd(const void* ei, int E, int e, int& s, int& d) {
    if (g_idx64) {
        const long long* p = (const long long*)ei;
        s = (int)p[e];
        d = (int)p[(size_t)E + e];
    } else {
        const int* p = (const int*)ei;
        s = p[e];
        d = p[E + e];
    }
}

__global__ void k_deg_count(const void* __restrict__ ei, const float* __restrict__ ew, int E) {
    int e = blockIdx.x * blockDim.x + threadIdx.x;
    if (e >= E) return;
    int s, d;
    edge_sd(ei, E, e, s, d);
    atomicAdd(&g_deg[d], ew[e]);
    atomicAdd(&g_cnt[d], 1);
}

// -------- parallel scan: block partial sums --------
__global__ void k_scan_part(int n) {
    __shared__ int sh[8];
    int i = blockIdx.x * 256 + threadIdx.x;
    int v = (i < n) ? g_cnt[i] : 0;
    int lane = threadIdx.x & 31, wid = threadIdx.x >> 5;
    int s = v;
#pragma unroll
    for (int o = 1; o < 32; o <<= 1) {
        int t = __shfl_up_sync(0xFFFFFFFFu, s, o);
        if (lane >= o) s += t;
    }
    if (lane == 31) sh[wid] = s;
    __syncthreads();
    if (threadIdx.x == 0) {
        int tot = 0;
#pragma unroll
        for (int w = 0; w < 8; w++) tot += sh[w];
        g_part[blockIdx.x] = tot;
    }
}

// -------- downsweep (self-computes base from partials) + fused dinv --------
__global__ void k_downsweep(int n, int E) {
    __shared__ int wsum[8], wbase[8], sh_base;
    int tid = threadIdx.x;
    int lane = tid & 31, wid = tid >> 5;
    int acc = 0;
    for (int i = tid; i < blockIdx.x; i += 256) acc += g_part[i];
#pragma unroll
    for (int o = 16; o > 0; o >>= 1) acc += __shfl_down_sync(0xFFFFFFFFu, acc, o);
    if (lane == 0) wsum[wid] = acc;
    __syncthreads();
    if (tid == 0) {
        int b = 0;
#pragma unroll
        for (int w = 0; w < 8; w++) b += wsum[w];
        sh_base = b;
    }
    __syncthreads();

    int i = blockIdx.x * 256 + tid;
    int v = (i < n) ? g_cnt[i] : 0;
    int s = v;
#pragma unroll
    for (int o = 1; o < 32; o <<= 1) {
        int t = __shfl_up_sync(0xFFFFFFFFu, s, o);
        if (lane >= o) s += t;
    }
    if (lane == 31) wsum[wid] = s;
    __syncthreads();
    if (tid == 0) {
        int a2 = 0;
#pragma unroll
        for (int w = 0; w < 8; w++) { wbase[w] = a2; a2 += wsum[w]; }
    }
    __syncthreads();
    if (i < n) {
        int ex = sh_base + wbase[wid] + s - v;
        g_off[i] = ex;
        g_cur[i] = ex;
        g_dinv[i] = rsqrtf(g_deg[i] + 1.0f);   // +1 self loop
    }
    if (i == 0) g_off[n] = E;
}

__global__ void k_scatter(const void* __restrict__ ei, const float* __restrict__ ew, int E) {
    int e = blockIdx.x * blockDim.x + threadIdx.x;
    if (e >= E) return;
    int s, d;
    edge_sd(ei, E, e, s, d);
    int pos = atomicAdd(&g_cur[d], 1);
    g_csr_src[pos]  = s;
    g_csr_norm[pos] = g_dinv[s] * ew[e] * g_dinv[d];
}

// -------- GEMM: Y[n,NC] = X[n,128] @ W[128,NC]; 128xNC tile, packed f32x2 FMA --------
template <int NC, bool HALF_OUT>
__launch_bounds__(256, 2)
__global__ void k_gemm(const float* __restrict__ X, const float* __restrict__ W,
                       void* __restrict__ Yv, int n) {
    const int K  = 128;
    const int KB = 32;
    const int NG = NC / 64;
    const int CT = NG * 4;

    __shared__ float Ws[KB][NC];
    __shared__ float Xs[KB][132];

    int tid = threadIdx.x;
    int tx = tid & 15;
    int ty = tid >> 4;
    int row0 = blockIdx.x * 128;

    unsigned long long acc[4][CT];
#pragma unroll
    for (int i = 0; i < 4; i++)
#pragma unroll
        for (int j = 0; j < CT; j++) acc[i][j] = 0ull;

    for (int kt = 0; kt < K; kt += KB) {
        {
            const float4* W4 = (const float4*)(W + (size_t)kt * NC);
            float4* Ws4 = (float4*)&Ws[0][0];
#pragma unroll
            for (int i = tid; i < KB * NC / 4; i += 256) Ws4[i] = W4[i];
        }
#pragma unroll
        for (int i = 0; i < 4; i++) {
            int idx = tid + 256 * i;
            int r = idx >> 3, c = idx & 7;
            int row = row0 + r;
            float4 v = make_float4(0.f, 0.f, 0.f, 0.f);
            if (row < n) v = *(const float4*)&X[(size_t)row * K + kt + 4 * c];
            Xs[4 * c + 0][r] = v.x;
            Xs[4 * c + 1][r] = v.y;
            Xs[4 * c + 2][r] = v.z;
            Xs[4 * c + 3][r] = v.w;
        }
        __syncthreads();

#pragma unroll
        for (int k = 0; k < KB; k++) {
            const ulonglong2* xr2 = (const ulonglong2*)&Xs[k][ty * 8];
            ulonglong2 xa = xr2[0], xb = xr2[1];
            unsigned long long xp[4] = {xa.x, xa.y, xb.x, xb.y};
            unsigned long long wd[CT];
#pragma unroll
            for (int g = 0; g < NG; g++) {
                float4 w4 = *(const float4*)&Ws[k][g * 64 + tx * 4];
                PACK_DUP_F32X2(wd[g * 4 + 0], w4.x);
                PACK_DUP_F32X2(wd[g * 4 + 1], w4.y);
                PACK_DUP_F32X2(wd[g * 4 + 2], w4.z);
                PACK_DUP_F32X2(wd[g * 4 + 3], w4.w);
            }
#pragma unroll
            for (int i = 0; i < 4; i++)
#pragma unroll
                for (int j = 0; j < CT; j++)
                    FMA_F32X2(acc[i][j], xp[i], wd[j], acc[i][j]);
        }
        __syncthreads();
    }

#pragma unroll
    for (int i2 = 0; i2 < 4; i2++) {
        float lo[CT], hi[CT];
#pragma unroll
        for (int j = 0; j < CT; j++) {
            uint32_t l, h;
            UNPACK_F32X2(l, h, acc[i2][j]);
            lo[j] = __uint_as_float(l);
            hi[j] = __uint_as_float(h);
        }
        int rowa = row0 + ty * 8 + 2 * i2;
        int rowb = rowa + 1;
        if (HALF_OUT) {
            __half* Y = (__half*)Yv;
            if (rowa < n) {
#pragma unroll
                for (int g = 0; g < NG; g++) {
                    __half2 p0 = __floats2half2_rn(lo[g * 4 + 0], lo[g * 4 + 1]);
                    __half2 p1 = __floats2half2_rn(lo[g * 4 + 2], lo[g * 4 + 3]);
                    uint2 o = {*(uint32_t*)&p0, *(uint32_t*)&p1};
                    *(uint2*)&Y[(size_t)rowa * NC + g * 64 + tx * 4] = o;
                }
            }
            if (rowb < n) {
#pragma unroll
                for (int g = 0; g < NG; g++) {
                    __half2 p0 = __floats2half2_rn(hi[g * 4 + 0], hi[g * 4 + 1]);
                    __half2 p1 = __floats2half2_rn(hi[g * 4 + 2], hi[g * 4 + 3]);
                    uint2 o = {*(uint32_t*)&p0, *(uint32_t*)&p1};
                    *(uint2*)&Y[(size_t)rowb * NC + g * 64 + tx * 4] = o;
                }
            }
        } else {
            float* Y = (float*)Yv;
            if (rowa < n) {
#pragma unroll
                for (int g = 0; g < NG; g++) {
                    float4 o = {lo[g * 4], lo[g * 4 + 1], lo[g * 4 + 2], lo[g * 4 + 3]};
                    *(float4*)&Y[(size_t)rowa * NC + g * 64 + tx * 4] = o;
                }
            }
            if (rowb < n) {
#pragma unroll
                for (int g = 0; g < NG; g++) {
                    float4 o = {hi[g * 4], hi[g * 4 + 1], hi[g * 4 + 2], hi[g * 4 + 3]};
                    *(float4*)&Y[(size_t)rowb * NC + g * 64 + tx * 4] = o;
                }
            }
        }
    }
}

// -------- layer-1 aggregation (128 ch, fp16): warp/node, coalesced index staging --------
// Row = 128 half = 32 lanes x 8B. Lane e loads (src, norm) for edge beg+e in ONE
// coalesced pass; inner loop shfl-broadcasts so all gathers are independent (MLP~deg).
__launch_bounds__(256)
__global__ void k_agg1(const float* __restrict__ b1, int n) {
    int gw = (blockIdx.x * 256 + threadIdx.x) >> 5;
    int lane = threadIdx.x & 31;
    if (gw >= n) return;

    const uint2* __restrict__ xw = (const uint2*)g_xw1h;
    const int*   __restrict__ csr = g_csr_src;
    const float* __restrict__ nrm = g_csr_norm;
    int beg = g_off[gw], end = g_off[gw + 1];

    float ax = 0.f, ay = 0.f, az = 0.f, aw = 0.f;
    for (int base = beg; base < end; base += 32) {
        int m = end - base; if (m > 32) m = 32;
        int  idx = 0; float wv = 0.f;
        if (base + lane < end) {
            idx = __ldg(&csr[base + lane]);
            wv  = __ldg(&nrm[base + lane]);
        }
        int j = 0;
        for (; j + 2 <= m; j += 2) {
            int   s0 = __shfl_sync(0xFFFFFFFFu, idx, j);
            float w0 = __shfl_sync(0xFFFFFFFFu, wv, j);
            int   s1 = __shfl_sync(0xFFFFFFFFu, idx, j + 1);
            float w1 = __shfl_sync(0xFFFFFFFFu, wv, j + 1);
            uint2 u0 = xw[(size_t)s0 * 32 + lane];
            uint2 u1 = xw[(size_t)s1 * 32 + lane];
            float2 a0 = __half22float2(*(__half2*)&u0.x);
            float2 c0 = __half22float2(*(__half2*)&u0.y);
            float2 a1 = __half22float2(*(__half2*)&u1.x);
            float2 c1 = __half22float2(*(__half2*)&u1.y);
            ax += w0 * a0.x + w1 * a1.x;
            ay += w0 * a0.y + w1 * a1.y;
            az += w0 * c0.x + w1 * c1.x;
            aw += w0 * c0.y + w1 * c1.y;
        }
        if (j < m) {
            int   s = __shfl_sync(0xFFFFFFFFu, idx, j);
            float w = __shfl_sync(0xFFFFFFFFu, wv, j);
            uint2 u = xw[(size_t)s * 32 + lane];
            float2 a = __half22float2(*(__half2*)&u.x);
            float2 c = __half22float2(*(__half2*)&u.y);
            ax += w * a.x; ay += w * a.y; az += w * c.x; aw += w * c.y;
        }
    }
    float di = g_dinv[gw];
    float sn = di * di;
    {
        uint2 u = xw[(size_t)gw * 32 + lane];
        float2 a = __half22float2(*(__half2*)&u.x);
        float2 c = __half22float2(*(__half2*)&u.y);
        ax += sn * a.x; ay += sn * a.y; az += sn * c.x; aw += sn * c.y;
    }

    float4 bb = ((const float4*)b1)[lane];
    ax += bb.x; ay += bb.y; az += bb.z; aw += bb.w;

    float4 o;
    o.x = (ax > 0.f) ? ax : expm1f(ax);
    o.y = (ay > 0.f) ? ay : expm1f(ay);
    o.z = (az > 0.f) ? az : expm1f(az);
    o.w = (aw > 0.f) ? aw : expm1f(aw);
    ((float4*)g_h)[(size_t)gw * 32 + lane] = o;
}

// -------- layer-2 aggregation (64 ch, fp16): same staging scheme --------
__device__ __forceinline__ float softplus_f(float v) {
    return fmaxf(v, 0.0f) + log1pf(expf(-fabsf(v)));
}

__launch_bounds__(256)
__global__ void k_agg2(const float* __restrict__ b2, float* __restrict__ out, int n) {
    int gw = (blockIdx.x * 256 + threadIdx.x) >> 5;
    int lane = threadIdx.x & 31;
    if (gw >= n) return;

    const uint32_t* __restrict__ xw = (const uint32_t*)g_xw2h;
    const int*   __restrict__ csr = g_csr_src;
    const float* __restrict__ nrm = g_csr_norm;
    int beg = g_off[gw], end = g_off[gw + 1];

    float ax = 0.f, ay = 0.f;
    for (int base = beg; base < end; base += 32) {
        int m = end - base; if (m > 32) m = 32;
        int  idx = 0; float wv = 0.f;
        if (base + lane < end) {
            idx = __ldg(&csr[base + lane]);
            wv  = __ldg(&nrm[base + lane]);
        }
        int j = 0;
        for (; j + 2 <= m; j += 2) {
            int   s0 = __shfl_sync(0xFFFFFFFFu, idx, j);
            float w0 = __shfl_sync(0xFFFFFFFFu, wv, j);
            int   s1 = __shfl_sync(0xFFFFFFFFu, idx, j + 1);
            float w1 = __shfl_sync(0xFFFFFFFFu, wv, j + 1);
            uint32_t u0 = xw[(size_t)s0 * 32 + lane];
            uint32_t u1 = xw[(size_t)s1 * 32 + lane];
            float2 v0 = __half22float2(*(__half2*)&u0);
            float2 v1 = __half22float2(*(__half2*)&u1);
            ax += w0 * v0.x + w1 * v1.x;
            ay += w0 * v0.y + w1 * v1.y;
        }
        if (j < m) {
            int   s = __shfl_sync(0xFFFFFFFFu, idx, j);
            float w = __shfl_sync(0xFFFFFFFFu, wv, j);
            uint32_t u = xw[(size_t)s * 32 + lane];
            float2 v = __half22float2(*(__half2*)&u);
            ax += w * v.x; ay += w * v.y;
        }
    }
    float di = g_dinv[gw];
    float sn = di * di;
    {
        uint32_t u = xw[(size_t)gw * 32 + lane];
        float2 v = __half22float2(*(__half2*)&u);
        ax += sn * v.x; ay += sn * v.y;
    }

    float2 bb = ((const float2*)b2)[lane];
    ax += bb.x; ay += bb.y;

    float2 o;
    o.x = softplus_f(ax) + 1e-4f;
    o.y = softplus_f(ay) + 1e-4f;
    ((float2*)out)[(size_t)gw * 32 + lane] = o;
}

// -------- launcher --------
extern "C" void kernel_launch(void* const* d_in, const int* in_sizes, int n_in,
                              void* d_out, int out_size) {
    const float* x  = (const float*)d_in[0];
    const void*  ei = d_in[1];
    const float* ew = (const float*)d_in[2];
    const float* W1 = (const float*)d_in[3];
    const float* b1 = (const float*)d_in[4];
    const float* W2 = (const float*)d_in[5];
    const float* b2 = (const float*)d_in[6];
    float* out = (float*)d_out;

    int n = in_sizes[0] / CIN;   // 50000
    int E = in_sizes[2];         // 800000

    void *xw1p, *hp, *xw2p;
    cudaGetSymbolAddress(&xw1p, g_xw1h);
    cudaGetSymbolAddress(&hp,   g_h);
    cudaGetSymbolAddress(&xw2p, g_xw2h);

    int nb = (n + 255) / 256;
    int eb = (E + 255) / 256;
    int ab = (n * 32 + 255) / 256;
    int gb = (n + 127) / 128;

    k_zero<<<nb, 256>>>((const int*)ei, 2 * E, n);
    k_deg_count<<<eb, 256>>>(ei, ew, E);
    k_scan_part<<<nb, 256>>>(n);
    k_downsweep<<<nb, 256>>>(n, E);
    k_scatter<<<eb, 256>>>(ei, ew, E);

    k_gemm<CHID, true><<<gb, 256>>>(x, W1, xw1p, n);
    k_agg1<<<ab, 256>>>(b1, n);
    k_gemm<COUT, true><<<gb, 256>>>((const float*)hp, W2, xw2p, n);
    k_agg2<<<ab, 256>>>(b2, out, n);
}

// round 10
// speedup vs baseline: 1.1457x; 1.1457x over previous
#include <cuda_runtime.h>
#include <cuda_fp16.h>
#include <math.h>
#include <stdint.h>

// N=50000, E=800000, C_IN=128, C_HID=128, C_OUT=64
#define CIN  128
#define CHID 128
#define COUT 64
#define MAXN 50048
#define MAXE 800000
#define NCHK 196      // ceil(50000/256)
#define G1   148      // CSR blocks participating in grid barrier
#define GRID_FUSED 296

// -------- scratch (device globals) --------
__device__ float g_deg[MAXN];
__device__ float g_dinv[MAXN];
__device__ int   g_cnt[MAXN];
__device__ int   g_off[MAXN + 1];
__device__ int   g_cur[MAXN];
__device__ int   g_part[NCHK + 4];
__device__ int   g_csr_src[MAXE];
__device__ float g_csr_norm[MAXE];
__device__ __half g_xw1h[(size_t)MAXN * CHID];
__device__ float  g_h  [(size_t)MAXN * CHID];
__device__ __half g_xw2h[(size_t)MAXN * COUT];
__device__ int   g_idx64;
__device__ unsigned long long g_bcnt;   // monotonic barrier counter (never reset)
__device__ unsigned long long g_bbase;  // counter value at launch start (handed off)

// -------- packed f32x2 helpers --------
#define FMA_F32X2(d, a, b, c) \
    asm("fma.rn.f32x2 %0, %1, %2, %3;" : "=l"(d) : "l"(a), "l"(b), "l"(c))
#define PACK_DUP_F32X2(out, f) \
    asm("mov.b64 %0, {%1, %1};" : "=l"(out) : "r"(__float_as_uint(f)))
#define UNPACK_F32X2(lo, hi, in) \
    asm("mov.b64 {%0, %1}, %2;" : "=r"(lo), "=r"(hi) : "l"(in))

__device__ __forceinline__ void edge_sd(const void* ei, int E, int e, int& s, int& d) {
    if (g_idx64) {
        const long long* p = (const long long*)ei;
        s = (int)p[e];
        d = (int)p[(size_t)E + e];
    } else {
        const int* p = (const int*)ei;
        s = p[e];
        d = p[E + e];
    }
}

// -------- grid barrier over the G1 CSR blocks (monotonic ticket counter) --------
__device__ __forceinline__ void gbar(unsigned long long bb, int idx) {
    __syncthreads();
    if (threadIdx.x == 0) {
        __threadfence();
        unsigned long long target = bb + (unsigned long long)idx * G1;
        unsigned long long t = atomicAdd(&g_bcnt, 1ULL);
        if (idx == 4 && t == target - 1) {
            // last arriver of the last barrier: hand base to the next launch
            *(volatile unsigned long long*)&g_bbase = bb + 4ULL * G1;
        }
        volatile unsigned long long* p = (volatile unsigned long long*)&g_bcnt;
        while (*p < target) __nanosleep(64);
        __threadfence();
    }
    __syncthreads();
}

// -------- GEMM tile body: Y[row0..row0+127, :] = X @ W, f32x2 FMA --------
template <int NC, bool HALF_OUT>
__device__ __forceinline__ void gemm_tile(const float* __restrict__ X,
                                          const float* __restrict__ W,
                                          void* __restrict__ Yv, int n, int row0,
                                          float (*Ws)[NC], float (*Xs)[132]) {
    const int K  = 128;
    const int KB = 32;
    const int NG = NC / 64;
    const int CT = NG * 4;

    int tid = threadIdx.x;
    int tx = tid & 15;
    int ty = tid >> 4;

    unsigned long long acc[4][CT];
#pragma unroll
    for (int i = 0; i < 4; i++)
#pragma unroll
        for (int j = 0; j < CT; j++) acc[i][j] = 0ull;

    for (int kt = 0; kt < K; kt += KB) {
        {
            const float4* W4 = (const float4*)(W + (size_t)kt * NC);
            float4* Ws4 = (float4*)&Ws[0][0];
#pragma unroll
            for (int i = tid; i < KB * NC / 4; i += 256) Ws4[i] = W4[i];
        }
#pragma unroll
        for (int i = 0; i < 4; i++) {
            int idx = tid + 256 * i;
            int r = idx >> 3, c = idx & 7;
            int row = row0 + r;
            float4 v = make_float4(0.f, 0.f, 0.f, 0.f);
            if (row < n) v = *(const float4*)&X[(size_t)row * K + kt + 4 * c];
            Xs[4 * c + 0][r] = v.x;
            Xs[4 * c + 1][r] = v.y;
            Xs[4 * c + 2][r] = v.z;
            Xs[4 * c + 3][r] = v.w;
        }
        __syncthreads();

#pragma unroll
        for (int k = 0; k < KB; k++) {
            const ulonglong2* xr2 = (const ulonglong2*)&Xs[k][ty * 8];
            ulonglong2 xa = xr2[0], xb = xr2[1];
            unsigned long long xp[4] = {xa.x, xa.y, xb.x, xb.y};
            unsigned long long wd[CT];
#pragma unroll
            for (int g = 0; g < NG; g++) {
                float4 w4 = *(const float4*)&Ws[k][g * 64 + tx * 4];
                PACK_DUP_F32X2(wd[g * 4 + 0], w4.x);
                PACK_DUP_F32X2(wd[g * 4 + 1], w4.y);
                PACK_DUP_F32X2(wd[g * 4 + 2], w4.z);
                PACK_DUP_F32X2(wd[g * 4 + 3], w4.w);
            }
#pragma unroll
            for (int i = 0; i < 4; i++)
#pragma unroll
                for (int j = 0; j < CT; j++)
                    FMA_F32X2(acc[i][j], xp[i], wd[j], acc[i][j]);
        }
        __syncthreads();
    }

#pragma unroll
    for (int i2 = 0; i2 < 4; i2++) {
        float lo[CT], hi[CT];
#pragma unroll
        for (int j = 0; j < CT; j++) {
            uint32_t l, h;
            UNPACK_F32X2(l, h, acc[i2][j]);
            lo[j] = __uint_as_float(l);
            hi[j] = __uint_as_float(h);
        }
        int rowa = row0 + ty * 8 + 2 * i2;
        int rowb = rowa + 1;
        if (HALF_OUT) {
            __half* Y = (__half*)Yv;
            if (rowa < n) {
#pragma unroll
                for (int g = 0; g < NG; g++) {
                    __half2 p0 = __floats2half2_rn(lo[g * 4 + 0], lo[g * 4 + 1]);
                    __half2 p1 = __floats2half2_rn(lo[g * 4 + 2], lo[g * 4 + 3]);
                    uint2 o = {*(uint32_t*)&p0, *(uint32_t*)&p1};
                    *(uint2*)&Y[(size_t)rowa * NC + g * 64 + tx * 4] = o;
                }
            }
            if (rowb < n) {
#pragma unroll
                for (int g = 0; g < NG; g++) {
                    __half2 p0 = __floats2half2_rn(hi[g * 4 + 0], hi[g * 4 + 1]);
                    __half2 p1 = __floats2half2_rn(hi[g * 4 + 2], hi[g * 4 + 3]);
                    uint2 o = {*(uint32_t*)&p0, *(uint32_t*)&p1};
                    *(uint2*)&Y[(size_t)rowb * NC + g * 64 + tx * 4] = o;
                }
            }
        } else {
            float* Y = (float*)Yv;
            if (rowa < n) {
#pragma unroll
                for (int g = 0; g < NG; g++) {
                    float4 o = {lo[g * 4], lo[g * 4 + 1], lo[g * 4 + 2], lo[g * 4 + 3]};
                    *(float4*)&Y[(size_t)rowa * NC + g * 64 + tx * 4] = o;
                }
            }
            if (rowb < n) {
#pragma unroll
                for (int g = 0; g < NG; g++) {
                    float4 o = {hi[g * 4], hi[g * 4 + 1], hi[g * 4 + 2], hi[g * 4 + 3]};
                    *(float4*)&Y[(size_t)rowb * NC + g * 64 + tx * 4] = o;
                }
            }
        }
    }
}

// -------- FUSED: blocks 0..147 build CSR (5 phases, grid barriers); 148..295 run GEMM1 --------
__global__ void __launch_bounds__(256, 2)
k_fused(const float* __restrict__ x, const void* __restrict__ ei,
        const float* __restrict__ ew, const float* __restrict__ W1,
        __half* __restrict__ xw1, int n, int E) {
    __shared__ float Ws[32][CHID];
    __shared__ float Xs[32][132];
    __shared__ int wsA[8], wsB[8], wbase[8];
    __shared__ int sh_cb;
    __shared__ unsigned long long sh_bb;

    int tid = threadIdx.x;

    if (blockIdx.x >= G1) {
        // ---- GEMM1 role ----
        int t = blockIdx.x - G1;
        int ntiles = (n + 127) >> 7;
        for (; t < ntiles; t += GRID_FUSED - G1)
            gemm_tile<CHID, true>(x, W1, xw1, n, t << 7, Ws, Xs);
        return;
    }

    // ---- CSR role (148 blocks) ----
    int cid = blockIdx.x;
    int lane = tid & 31, wid = tid >> 5;
    const int NT = G1 * 256;   // threads in CSR role

    if (tid == 0) sh_bb = *(volatile unsigned long long*)&g_bbase;
    __syncthreads();
    unsigned long long bb = sh_bb;

    // Phase A: zero + idx64 detect
    for (int i = cid * 256 + tid; i < n; i += NT) { g_deg[i] = 0.0f; g_cnt[i] = 0; }
    if (cid == 0 && tid < 32) {
        const int* p = (const int*)ei;
        int words = 2 * E;
        int i1 = 1 + 2 * tid, i2 = 65 + 2 * tid;
        int nz = 0;
        if (i1 < words && p[i1] != 0) nz = 1;
        if (i2 < words && p[i2] != 0) nz = 1;
        unsigned b = __ballot_sync(0xFFFFFFFFu, nz);
        if (tid == 0) g_idx64 = (b == 0u) ? 1 : 0;
    }
    gbar(bb, 1);

    // Phase B: degree + count
    for (int e = cid * 256 + tid; e < E; e += NT) {
        int s, d;
        edge_sd(ei, E, e, s, d);
        atomicAdd(&g_deg[d], __ldg(&ew[e]));
        atomicAdd(&g_cnt[d], 1);
    }
    gbar(bb, 2);

    // Phase C: per-chunk partial sums (chunk = 256 nodes)
    int nch = (n + 255) >> 8;
    for (int chunk = cid; chunk < nch; chunk += G1) {
        int i = chunk * 256 + tid;
        int v = (i < n) ? __ldcg(&g_cnt[i]) : 0;
        int s = v;
#pragma unroll
        for (int o = 16; o > 0; o >>= 1) s += __shfl_down_sync(0xFFFFFFFFu, s, o);
        if (lane == 0) wsA[wid] = s;
        __syncthreads();
        if (tid == 0) {
            int tot = 0;
#pragma unroll
            for (int w = 0; w < 8; w++) tot += wsA[w];
            g_part[chunk] = tot;
        }
        __syncthreads();
    }
    gbar(bb, 3);

    // Phase D: downsweep (base from partials) + dinv
    for (int chunk = cid; chunk < nch; chunk += G1) {
        int acc = 0;
        for (int c = tid; c < chunk; c += 256) acc += __ldcg(&g_part[c]);
#pragma unroll
        for (int o = 16; o > 0; o >>= 1) acc += __shfl_down_sync(0xFFFFFFFFu, acc, o);
        if (lane == 0) wsA[wid] = acc;
        __syncthreads();
        if (tid == 0) {
            int b = 0;
#pragma unroll
            for (int w = 0; w < 8; w++) b += wsA[w];
            sh_cb = b;
        }
        __syncthreads();

        int i = chunk * 256 + tid;
        int v = (i < n) ? __ldcg(&g_cnt[i]) : 0;
        int s = v;
#pragma unroll
        for (int o = 1; o < 32; o <<= 1) {
            int t = __shfl_up_sync(0xFFFFFFFFu, s, o);
            if (lane >= o) s += t;
        }
        if (lane == 31) wsB[wid] = s;
        __syncthreads();
        if (tid == 0) {
            int a2 = 0;
#pragma unroll
            for (int w = 0; w < 8; w++) { wbase[w] = a2; a2 += wsB[w]; }
        }
        __syncthreads();
        if (i < n) {
            int ex = sh_cb + wbase[wid] + s - v;
            g_off[i] = ex;
            g_cur[i] = ex;
            g_dinv[i] = rsqrtf(__ldcg(&g_deg[i]) + 1.0f);   // +1 self loop
        }
        __syncthreads();
    }
    if (cid == 0 && tid == 0) g_off[n] = E;
    gbar(bb, 4);

    // Phase E: scatter
    for (int e = cid * 256 + tid; e < E; e += NT) {
        int s, d;
        edge_sd(ei, E, e, s, d);
        int pos = atomicAdd(&g_cur[d], 1);
        g_csr_src[pos]  = s;
        g_csr_norm[pos] = __ldcg(&g_dinv[s]) * __ldg(&ew[e]) * __ldcg(&g_dinv[d]);
    }
}

// -------- standalone GEMM (layer 2) --------
template <int NC, bool HALF_OUT>
__launch_bounds__(256, 2)
__global__ void k_gemm(const float* __restrict__ X, const float* __restrict__ W,
                       void* __restrict__ Yv, int n) {
    __shared__ float Ws[32][NC];
    __shared__ float Xs[32][132];
    gemm_tile<NC, HALF_OUT>(X, W, Yv, n, blockIdx.x * 128, Ws, Xs);
}

// -------- layer-1 aggregation (128 ch, fp16): warp per node --------
__launch_bounds__(256)
__global__ void k_agg1(const float* __restrict__ b1, int n) {
    int gw = (blockIdx.x * 256 + threadIdx.x) >> 5;
    int lane = threadIdx.x & 31;
    if (gw >= n) return;

    const uint2* __restrict__ xw = (const uint2*)g_xw1h;
    const int*   __restrict__ csr = g_csr_src;
    const float* __restrict__ nrm = g_csr_norm;
    int beg = g_off[gw], end = g_off[gw + 1];

    float ax = 0.f, ay = 0.f, az = 0.f, aw = 0.f;
    int e = beg;
    for (; e + 2 <= end; e += 2) {
        int   s0 = __ldg(&csr[e]),  s1 = __ldg(&csr[e + 1]);
        float w0 = __ldg(&nrm[e]),  w1 = __ldg(&nrm[e + 1]);
        uint2 u0 = xw[(size_t)s0 * 32 + lane];
        uint2 u1 = xw[(size_t)s1 * 32 + lane];
        float2 a0 = __half22float2(*(__half2*)&u0.x);
        float2 c0 = __half22float2(*(__half2*)&u0.y);
        float2 a1 = __half22float2(*(__half2*)&u1.x);
        float2 c1 = __half22float2(*(__half2*)&u1.y);
        ax += w0 * a0.x + w1 * a1.x;
        ay += w0 * a0.y + w1 * a1.y;
        az += w0 * c0.x + w1 * c1.x;
        aw += w0 * c0.y + w1 * c1.y;
    }
    if (e < end) {
        int s = __ldg(&csr[e]);
        float w = __ldg(&nrm[e]);
        uint2 u = xw[(size_t)s * 32 + lane];
        float2 a = __half22float2(*(__half2*)&u.x);
        float2 c = __half22float2(*(__half2*)&u.y);
        ax += w * a.x; ay += w * a.y; az += w * c.x; aw += w * c.y;
    }
    float di = g_dinv[gw];
    float sn = di * di;
    {
        uint2 u = xw[(size_t)gw * 32 + lane];
        float2 a = __half22float2(*(__half2*)&u.x);
        float2 c = __half22float2(*(__half2*)&u.y);
        ax += sn * a.x; ay += sn * a.y; az += sn * c.x; aw += sn * c.y;
    }

    float4 bb = ((const float4*)b1)[lane];
    ax += bb.x; ay += bb.y; az += bb.z; aw += bb.w;

    float4 o;
    o.x = (ax > 0.f) ? ax : expm1f(ax);
    o.y = (ay > 0.f) ? ay : expm1f(ay);
    o.z = (az > 0.f) ? az : expm1f(az);
    o.w = (aw > 0.f) ? aw : expm1f(aw);
    ((float4*)g_h)[(size_t)gw * 32 + lane] = o;
}

// -------- layer-2 aggregation (64 ch, fp16) --------
__device__ __forceinline__ float softplus_f(float v) {
    return fmaxf(v, 0.0f) + log1pf(expf(-fabsf(v)));
}

__launch_bounds__(256)
__global__ void k_agg2(const float* __restrict__ b2, float* __restrict__ out, int n) {
    int gw = (blockIdx.x * 256 + threadIdx.x) >> 5;
    int lane = threadIdx.x & 31;
    if (gw >= n) return;

    const uint32_t* __restrict__ xw = (const uint32_t*)g_xw2h;
    const int*   __restrict__ csr = g_csr_src;
    const float* __restrict__ nrm = g_csr_norm;
    int beg = g_off[gw], end = g_off[gw + 1];

    float ax = 0.f, ay = 0.f;
    int e = beg;
    for (; e + 2 <= end; e += 2) {
        int   s0 = __ldg(&csr[e]),  s1 = __ldg(&csr[e + 1]);
        float w0 = __ldg(&nrm[e]),  w1 = __ldg(&nrm[e + 1]);
        uint32_t u0 = xw[(size_t)s0 * 32 + lane];
        uint32_t u1 = xw[(size_t)s1 * 32 + lane];
        float2 v0 = __half22float2(*(__half2*)&u0);
        float2 v1 = __half22float2(*(__half2*)&u1);
        ax += w0 * v0.x + w1 * v1.x;
        ay += w0 * v0.y + w1 * v1.y;
    }
    if (e < end) {
        int s = __ldg(&csr[e]);
        float w = __ldg(&nrm[e]);
        uint32_t u = xw[(size_t)s * 32 + lane];
        float2 v = __half22float2(*(__half2*)&u);
        ax += w * v.x; ay += w * v.y;
    }
    float di = g_dinv[gw];
    float sn = di * di;
    {
        uint32_t u = xw[(size_t)gw * 32 + lane];
        float2 v = __half22float2(*(__half2*)&u);
        ax += sn * v.x; ay += sn * v.y;
    }

    float2 bb = ((const float2*)b2)[lane];
    ax += bb.x; ay += bb.y;

    float2 o;
    o.x = softplus_f(ax) + 1e-4f;
    o.y = softplus_f(ay) + 1e-4f;
    ((float2*)out)[(size_t)gw * 32 + lane] = o;
}

// -------- launcher --------
extern "C" void kernel_launch(void* const* d_in, const int* in_sizes, int n_in,
                              void* d_out, int out_size) {
    const float* x  = (const float*)d_in[0];
    const void*  ei = d_in[1];
    const float* ew = (const float*)d_in[2];
    const float* W1 = (const float*)d_in[3];
    const float* b1 = (const float*)d_in[4];
    const float* W2 = (const float*)d_in[5];
    const float* b2 = (const float*)d_in[6];
    float* out = (float*)d_out;

    int n = in_sizes[0] / CIN;   // 50000
    int E = in_sizes[2];         // 800000

    void *xw1p, *hp, *xw2p;
    cudaGetSymbolAddress(&xw1p, g_xw1h);
    cudaGetSymbolAddress(&hp,   g_h);
    cudaGetSymbolAddress(&xw2p, g_xw2h);

    int ab = (n * 32 + 255) / 256;
    int gb = (n + 127) / 128;

    k_fused<<<GRID_FUSED, 256>>>(x, ei, ew, W1, (__half*)xw1p, n, E);
    k_agg1<<<ab, 256>>>(b1, n);
    k_gemm<COUT, true><<<gb, 256>>>((const float*)hp, W2, xw2p, n);
    k_agg2<<<ab, 256>>>(b2, out, n);
}